// round 10
// baseline (speedup 1.0000x reference)
#include <cuda_runtime.h>
#include <cstdint>

#define N_MAX 100000
#define E_MAX 1200000
#define D 64
#define TILE 128
#define NT_MAX 1024   // >= ceil(N_MAX/TILE) = 782

__device__ __align__(16) int   g_deg  [N_MAX];
__device__ __align__(16) float g_dinv [N_MAX];
__device__ __align__(16) int   g_tcnt [NT_MAX];   // edges per src tile
__device__ __align__(16) int   g_toff [NT_MAX];   // tile start in g_tedge
__device__ __align__(16) int   g_tcur [NT_MAX];   // fill cursor
__device__ __align__(16) int2  g_tedge[E_MAX];    // (src, dst) bucketed by src tile
__device__ __align__(16) float g_hs   [N_MAX * D];
__device__ __align__(16) float g_agg  [N_MAX * D];

// ---------------- degree + tile histogram ----------------

__global__ void k_init(int n, int nt) {
    int i = blockIdx.x * blockDim.x + threadIdx.x;
    if (i < n)  g_deg[i]  = 1;                 // self-loop
    if (i < nt) g_tcnt[i] = 0;
}

__global__ void k_count(const int* __restrict__ ei, int E) {
    int e = blockIdx.x * blockDim.x + threadIdx.x;
    if (e >= E) return;
    atomicAdd(&g_deg[ei[E + e]], 1);           // in-degree (dst)
    atomicAdd(&g_tcnt[ei[e] / TILE], 1);       // src-tile histogram
}

__global__ void k_dinv(int n) {
    int i = blockIdx.x * blockDim.x + threadIdx.x;
    if (i < n) g_dinv[i] = rsqrtf((float)g_deg[i]);
}

// ---------------- tile offsets: exclusive scan over <=1024 tiles ----------------

__global__ void __launch_bounds__(1024, 1) k_tscan(int nt) {
    __shared__ int part[1024];
    int t = threadIdx.x;
    int v = (t < nt) ? g_tcnt[t] : 0;
    part[t] = v;
    __syncthreads();
    #pragma unroll
    for (int off = 1; off < 1024; off <<= 1) {
        int u = (t >= off) ? part[t - off] : 0;
        __syncthreads();
        part[t] += u;
        __syncthreads();
    }
    if (t < nt) {
        int excl = part[t] - v;
        g_toff[t] = excl;
        g_tcur[t] = excl;
    }
}

// ---------------- bucket fill: edge records grouped by src tile ----------------

__global__ void k_tfill(const int* __restrict__ ei, int E) {
    int e = blockIdx.x * blockDim.x + threadIdx.x;
    if (e >= E) return;
    int src = ei[e];
    int dst = ei[E + e];
    int pos = atomicAdd(&g_tcur[src / TILE], 1);
    g_tedge[pos] = make_int2(src, dst);
}

// ---------------- fused GEMM ----------------
// mode 0: in = X (raw input)
// mode 1: in = prelu(g_agg * dinv + b, a)   (fused layer-1 epilogue)
// output: hs = (in @ W) * dinv ; agg = hs (self-loop init)

__global__ void __launch_bounds__(256, 2)
k_gemm(const float* __restrict__ X, const float* __restrict__ W,
       const float* __restrict__ bp, const float* __restrict__ ap,
       int n, int mode)
{
    __shared__ __align__(16) float  Ws[D * D];
    __shared__ __align__(16) float4 xs[64][16];
    int t = threadIdx.x;

    #pragma unroll
    for (int i = 0; i < 4; i++)
        ((float4*)Ws)[t + 256 * i] = ((const float4*)W)[t + 256 * i];

    int base = blockIdx.x * 64;

    #pragma unroll
    for (int r = 0; r < 4; r++) {
        int i = t + 256 * r;
        int node = base + (i >> 4);
        int k4 = i & 15;
        float4 v = make_float4(0.f, 0.f, 0.f, 0.f);
        if (node < n) {
            if (mode == 0) {
                v = ((const float4*)X)[(size_t)node * 16 + k4];
            } else {
                v = ((const float4*)g_agg)[(size_t)node * 16 + k4];
                float dv = g_dinv[node];
                float4 bb = ((const float4*)bp)[k4];
                float4 aa = ((const float4*)ap)[k4];
                v.x = v.x * dv + bb.x; v.x = (v.x >= 0.f) ? v.x : aa.x * v.x;
                v.y = v.y * dv + bb.y; v.y = (v.y >= 0.f) ? v.y : aa.y * v.y;
                v.z = v.z * dv + bb.z; v.z = (v.z >= 0.f) ? v.z : aa.z * v.z;
                v.w = v.w * dv + bb.w; v.w = (v.w >= 0.f) ? v.w : aa.w * v.w;
            }
        }
        xs[i >> 4][k4] = v;
    }
    __syncthreads();

    int j = t & 63, g = t >> 6;
    float wcol[D];
    #pragma unroll
    for (int k = 0; k < D; k++) wcol[k] = Ws[k * D + j];

    #pragma unroll
    for (int batch = 0; batch < 4; batch++) {
        int n0 = g * 16 + batch * 4;
        float acc0 = 0.f, acc1 = 0.f, acc2 = 0.f, acc3 = 0.f;
        #pragma unroll
        for (int k4 = 0; k4 < 16; k4++) {
            float4 x0 = xs[n0 + 0][k4];
            float4 x1 = xs[n0 + 1][k4];
            float4 x2 = xs[n0 + 2][k4];
            float4 x3 = xs[n0 + 3][k4];
            float w0 = wcol[4 * k4 + 0], w1 = wcol[4 * k4 + 1];
            float w2 = wcol[4 * k4 + 2], w3 = wcol[4 * k4 + 3];
            acc0 = fmaf(x0.x, w0, acc0); acc0 = fmaf(x0.y, w1, acc0);
            acc0 = fmaf(x0.z, w2, acc0); acc0 = fmaf(x0.w, w3, acc0);
            acc1 = fmaf(x1.x, w0, acc1); acc1 = fmaf(x1.y, w1, acc1);
            acc1 = fmaf(x1.z, w2, acc1); acc1 = fmaf(x1.w, w3, acc1);
            acc2 = fmaf(x2.x, w0, acc2); acc2 = fmaf(x2.y, w1, acc2);
            acc2 = fmaf(x2.z, w2, acc2); acc2 = fmaf(x2.w, w3, acc2);
            acc3 = fmaf(x3.x, w0, acc3); acc3 = fmaf(x3.y, w1, acc3);
            acc3 = fmaf(x3.z, w2, acc3); acc3 = fmaf(x3.w, w3, acc3);
        }
        float accs[4] = {acc0, acc1, acc2, acc3};
        #pragma unroll
        for (int q = 0; q < 4; q++) {
            int node = base + n0 + q;
            if (node < n) {
                float v = accs[q] * g_dinv[node];
                size_t o = (size_t)node * D + j;
                g_hs[o]  = v;
                g_agg[o] = v;                      // self-loop contribution
            }
        }
    }
}

// ---------------- src-tiled scatter: agg[dst] += hs[src] ----------------
// One block per src tile: stage the tile's hs rows in smem, then process the
// tile's edge bucket edge-parallel (16 lanes/edge), gather from smem, RED out.

__global__ void __launch_bounds__(256)
k_scatter_t(int n)
{
    __shared__ __align__(16) float4 hs_s[TILE][16];   // 32 KB
    int tile = blockIdx.x;
    int t0 = tile * TILE;
    int t = threadIdx.x;

    #pragma unroll
    for (int r = 0; r < 8; r++) {
        int i = t + 256 * r;                          // [0, 2048)
        int node = t0 + (i >> 4);
        float4 v = make_float4(0.f, 0.f, 0.f, 0.f);
        if (node < n) v = ((const float4*)g_hs)[(size_t)node * 16 + (i & 15)];
        hs_s[i >> 4][i & 15] = v;
    }
    __syncthreads();

    int s = g_toff[tile];
    int e = s + g_tcnt[tile];
    int grp = t >> 4, lane = t & 15;

    for (int i = s + grp; i < e; i += 16) {
        int2 ed = g_tedge[i];
        float4 v = hs_s[ed.x - t0][lane];
        float* p = g_agg + (size_t)ed.y * D + lane * 4;
        unsigned long long gp;
        asm volatile("cvta.to.global.u64 %0, %1;" : "=l"(gp) : "l"(p));
        asm volatile("red.global.add.v4.f32 [%0], {%1,%2,%3,%4};"
                     :: "l"(gp), "f"(v.x), "f"(v.y), "f"(v.z), "f"(v.w)
                     : "memory");
    }
}

// ---------------- final epilogue: out = prelu(agg*dinv + b, a) ----------------

__global__ void k_epi(const float* __restrict__ b, const float* __restrict__ a,
                      float* __restrict__ out, int n) {
    int tid = blockIdx.x * blockDim.x + threadIdx.x;
    int node = tid >> 4;
    if (node >= n) return;
    int q = tid & 15;
    float dinv = g_dinv[node];
    float4 v  = ((const float4*)g_agg)[(size_t)node * 16 + q];
    float4 bb = ((const float4*)b)[q];
    float4 aa = ((const float4*)a)[q];
    v.x = v.x * dinv + bb.x; v.x = (v.x >= 0.f) ? v.x : aa.x * v.x;
    v.y = v.y * dinv + bb.y; v.y = (v.y >= 0.f) ? v.y : aa.y * v.y;
    v.z = v.z * dinv + bb.z; v.z = (v.z >= 0.f) ? v.z : aa.z * v.z;
    v.w = v.w * dinv + bb.w; v.w = (v.w >= 0.f) ? v.w : aa.w * v.w;
    ((float4*)out)[(size_t)node * 16 + q] = v;
}

// ---------------- launch ----------------

extern "C" void kernel_launch(void* const* d_in, const int* in_sizes, int n_in,
                              void* d_out, int out_size) {
    const float* x  = (const float*)d_in[0];
    const int*   ei = (const int*)d_in[1];     // int32 (JAX x64 disabled)
    const float* W1 = (const float*)d_in[2];
    const float* b1 = (const float*)d_in[3];
    const float* a1 = (const float*)d_in[4];
    const float* W2 = (const float*)d_in[5];
    const float* b2 = (const float*)d_in[6];
    const float* a2 = (const float*)d_in[7];
    float* out = (float*)d_out;

    int n  = in_sizes[0] / D;
    int E  = in_sizes[1] / 2;
    int nt = (n + TILE - 1) / TILE;

    int nb_n   = (n + 255) / 256;
    int nb_e   = (E + 255) / 256;
    int nb_gm  = (n + 63) / 64;
    int nb_epi = (int)(((long long)n * 16 + 255) / 256);

    // degree / norm / src-tile CSR build (amortized over both layers)
    k_init  <<<nb_n, 256>>>(n, nt);
    k_count <<<nb_e, 256>>>(ei, E);
    k_dinv  <<<nb_n, 256>>>(n);
    k_tscan <<<1, 1024>>>(nt);
    k_tfill <<<nb_e, 256>>>(ei, E);

    // layer 1
    k_gemm     <<<nb_gm, 256>>>(x, W1, b1, a1, n, 0);
    k_scatter_t<<<nt, 256>>>(n);

    // layer 2 (layer-1 epilogue fused into GEMM staging)
    k_gemm     <<<nb_gm, 256>>>(x, W2, b1, a1, n, 1);
    k_scatter_t<<<nt, 256>>>(n);
    k_epi      <<<nb_epi, 256>>>(b2, a2, out, n);
}

// round 13
// speedup vs baseline: 1.5910x; 1.5910x over previous
#include <cuda_runtime.h>
#include <cstdint>

#define N_MAX 100000
#define D 64

__device__ __align__(16) int   g_deg [N_MAX];
__device__ __align__(16) float g_dinv[N_MAX];
__device__ __align__(16) float g_hs  [N_MAX * D];
__device__ __align__(16) float g_agg [N_MAX * D];

// ---------------- degree / norm ----------------

__global__ void k_init_deg(int n) {
    int i = blockIdx.x * blockDim.x + threadIdx.x;
    if (i < n) g_deg[i] = 1;                 // self-loop
}

__global__ void k_count(const int* __restrict__ ei, int E) {
    int e = blockIdx.x * blockDim.x + threadIdx.x;
    if (e < E) atomicAdd(&g_deg[ei[E + e]], 1);
}

__global__ void k_dinv(int n) {
    int i = blockIdx.x * blockDim.x + threadIdx.x;
    if (i < n) g_dinv[i] = rsqrtf((float)g_deg[i]);
}

// ---------------- fused GEMM, 4x4 register blocking ----------------
// mode 0: in = X (raw input)
// mode 1: in = prelu(g_agg * dinv + b, a)   (fused layer-1 epilogue)
// output: hs = (in @ W) * dinv ; agg = hs (self-loop init)
//
// Block tile: 64 nodes x 64 cols. Thread (tn = t>>4, tj = t&15) computes
// nodes [4tn,4tn+4) x cols [4tj,4tj+4): 16 fp32 accumulators.
// Per k4-step: 4 broadcast x LDS.128 + 4 w LDS.128 -> 64 FMA (8 FMA/LDS).

__global__ void __launch_bounds__(256, 2)
k_gemm(const float* __restrict__ X, const float* __restrict__ W,
       const float* __restrict__ bp, const float* __restrict__ ap,
       int n, int mode)
{
    __shared__ __align__(16) float  Wt[D][68];    // transposed W, padded row
    __shared__ __align__(16) float4 xs[64][16];
    int t = threadIdx.x;

    // stage W transposed: Wt[j][k] = W[k*64 + j]  (coalesced reads)
    #pragma unroll
    for (int r = 0; r < 16; r++) {
        int i = t + 256 * r;
        Wt[i & 63][i >> 6] = W[i];
    }

    int base = blockIdx.x * 64;

    // stage input tile (coalesced float4), fusing layer-1 epilogue in mode 1
    #pragma unroll
    for (int r = 0; r < 4; r++) {
        int i = t + 256 * r;
        int node = base + (i >> 4);
        int k4 = i & 15;
        float4 v = make_float4(0.f, 0.f, 0.f, 0.f);
        if (node < n) {
            if (mode == 0) {
                v = ((const float4*)X)[(size_t)node * 16 + k4];
            } else {
                v = ((const float4*)g_agg)[(size_t)node * 16 + k4];
                float dv = g_dinv[node];
                float4 bb = ((const float4*)bp)[k4];
                float4 aa = ((const float4*)ap)[k4];
                v.x = v.x * dv + bb.x; v.x = (v.x >= 0.f) ? v.x : aa.x * v.x;
                v.y = v.y * dv + bb.y; v.y = (v.y >= 0.f) ? v.y : aa.y * v.y;
                v.z = v.z * dv + bb.z; v.z = (v.z >= 0.f) ? v.z : aa.z * v.z;
                v.w = v.w * dv + bb.w; v.w = (v.w >= 0.f) ? v.w : aa.w * v.w;
            }
        }
        xs[i >> 4][k4] = v;
    }
    __syncthreads();

    int tj = t & 15, tn = t >> 4;
    int n0 = 4 * tn;          // local node base
    int c0 = 4 * tj;          // column base

    float4 acc0 = make_float4(0.f,0.f,0.f,0.f);   // acc[ni].{x,y,z,w} = cols c0..c0+3
    float4 acc1 = acc0, acc2 = acc0, acc3 = acc0;

    #pragma unroll
    for (int k4 = 0; k4 < 16; k4++) {
        float4 x0 = xs[n0 + 0][k4];
        float4 x1 = xs[n0 + 1][k4];
        float4 x2 = xs[n0 + 2][k4];
        float4 x3 = xs[n0 + 3][k4];
        float4 w0 = *(const float4*)&Wt[c0 + 0][4 * k4];
        float4 w1 = *(const float4*)&Wt[c0 + 1][4 * k4];
        float4 w2 = *(const float4*)&Wt[c0 + 2][4 * k4];
        float4 w3 = *(const float4*)&Wt[c0 + 3][4 * k4];

        acc0.x = fmaf(x0.x, w0.x, acc0.x); acc0.x = fmaf(x0.y, w0.y, acc0.x);
        acc0.x = fmaf(x0.z, w0.z, acc0.x); acc0.x = fmaf(x0.w, w0.w, acc0.x);
        acc0.y = fmaf(x0.x, w1.x, acc0.y); acc0.y = fmaf(x0.y, w1.y, acc0.y);
        acc0.y = fmaf(x0.z, w1.z, acc0.y); acc0.y = fmaf(x0.w, w1.w, acc0.y);
        acc0.z = fmaf(x0.x, w2.x, acc0.z); acc0.z = fmaf(x0.y, w2.y, acc0.z);
        acc0.z = fmaf(x0.z, w2.z, acc0.z); acc0.z = fmaf(x0.w, w2.w, acc0.z);
        acc0.w = fmaf(x0.x, w3.x, acc0.w); acc0.w = fmaf(x0.y, w3.y, acc0.w);
        acc0.w = fmaf(x0.z, w3.z, acc0.w); acc0.w = fmaf(x0.w, w3.w, acc0.w);

        acc1.x = fmaf(x1.x, w0.x, acc1.x); acc1.x = fmaf(x1.y, w0.y, acc1.x);
        acc1.x = fmaf(x1.z, w0.z, acc1.x); acc1.x = fmaf(x1.w, w0.w, acc1.x);
        acc1.y = fmaf(x1.x, w1.x, acc1.y); acc1.y = fmaf(x1.y, w1.y, acc1.y);
        acc1.y = fmaf(x1.z, w1.z, acc1.y); acc1.y = fmaf(x1.w, w1.w, acc1.y);
        acc1.z = fmaf(x1.x, w2.x, acc1.z); acc1.z = fmaf(x1.y, w2.y, acc1.z);
        acc1.z = fmaf(x1.z, w2.z, acc1.z); acc1.z = fmaf(x1.w, w2.w, acc1.z);
        acc1.w = fmaf(x1.x, w3.x, acc1.w); acc1.w = fmaf(x1.y, w3.y, acc1.w);
        acc1.w = fmaf(x1.z, w3.z, acc1.w); acc1.w = fmaf(x1.w, w3.w, acc1.w);

        acc2.x = fmaf(x2.x, w0.x, acc2.x); acc2.x = fmaf(x2.y, w0.y, acc2.x);
        acc2.x = fmaf(x2.z, w0.z, acc2.x); acc2.x = fmaf(x2.w, w0.w, acc2.x);
        acc2.y = fmaf(x2.x, w1.x, acc2.y); acc2.y = fmaf(x2.y, w1.y, acc2.y);
        acc2.y = fmaf(x2.z, w1.z, acc2.y); acc2.y = fmaf(x2.w, w1.w, acc2.y);
        acc2.z = fmaf(x2.x, w2.x, acc2.z); acc2.z = fmaf(x2.y, w2.y, acc2.z);
        acc2.z = fmaf(x2.z, w2.z, acc2.z); acc2.z = fmaf(x2.w, w2.w, acc2.z);
        acc2.w = fmaf(x2.x, w3.x, acc2.w); acc2.w = fmaf(x2.y, w3.y, acc2.w);
        acc2.w = fmaf(x2.z, w3.z, acc2.w); acc2.w = fmaf(x2.w, w3.w, acc2.w);

        acc3.x = fmaf(x3.x, w0.x, acc3.x); acc3.x = fmaf(x3.y, w0.y, acc3.x);
        acc3.x = fmaf(x3.z, w0.z, acc3.x); acc3.x = fmaf(x3.w, w0.w, acc3.x);
        acc3.y = fmaf(x3.x, w1.x, acc3.y); acc3.y = fmaf(x3.y, w1.y, acc3.y);
        acc3.y = fmaf(x3.z, w1.z, acc3.y); acc3.y = fmaf(x3.w, w1.w, acc3.y);
        acc3.z = fmaf(x3.x, w2.x, acc3.z); acc3.z = fmaf(x3.y, w2.y, acc3.z);
        acc3.z = fmaf(x3.z, w2.z, acc3.z); acc3.z = fmaf(x3.w, w2.w, acc3.z);
        acc3.w = fmaf(x3.x, w3.x, acc3.w); acc3.w = fmaf(x3.y, w3.y, acc3.w);
        acc3.w = fmaf(x3.z, w3.z, acc3.w); acc3.w = fmaf(x3.w, w3.w, acc3.w);
    }

    float4 accs[4] = {acc0, acc1, acc2, acc3};
    #pragma unroll
    for (int q = 0; q < 4; q++) {
        int node = base + n0 + q;
        if (node < n) {
            float dv = g_dinv[node];
            float4 v = accs[q];
            v.x *= dv; v.y *= dv; v.z *= dv; v.w *= dv;
            size_t o = (size_t)node * 16 + tj;          // float4 index
            ((float4*)g_hs)[o]  = v;
            ((float4*)g_agg)[o] = v;                    // self-loop contribution
        }
    }
}

// ---------------- edge scatter: agg[dst] += hs[src] ----------------

__global__ void k_scatter(const int* __restrict__ ei, int E) {
    int tid = blockIdx.x * blockDim.x + threadIdx.x;
    int e = tid >> 4;
    if (e >= E) return;
    int lane = tid & 15;
    int src = ei[e];
    int dst = ei[E + e];
    float4 v = ((const float4*)(g_hs + (size_t)src * D))[lane];
    float* p = g_agg + (size_t)dst * D + lane * 4;
    unsigned long long gp;
    asm volatile("cvta.to.global.u64 %0, %1;" : "=l"(gp) : "l"(p));
    asm volatile("red.global.add.v4.f32 [%0], {%1,%2,%3,%4};"
                 :: "l"(gp), "f"(v.x), "f"(v.y), "f"(v.z), "f"(v.w)
                 : "memory");
}

// ---------------- final epilogue: out = prelu(agg*dinv + b, a) ----------------

__global__ void k_epi(const float* __restrict__ b, const float* __restrict__ a,
                      float* __restrict__ out, int n) {
    int tid = blockIdx.x * blockDim.x + threadIdx.x;
    int node = tid >> 4;
    if (node >= n) return;
    int q = tid & 15;
    float dinv = g_dinv[node];
    float4 v  = ((const float4*)g_agg)[(size_t)node * 16 + q];
    float4 bb = ((const float4*)b)[q];
    float4 aa = ((const float4*)a)[q];
    v.x = v.x * dinv + bb.x; v.x = (v.x >= 0.f) ? v.x : aa.x * v.x;
    v.y = v.y * dinv + bb.y; v.y = (v.y >= 0.f) ? v.y : aa.y * v.y;
    v.z = v.z * dinv + bb.z; v.z = (v.z >= 0.f) ? v.z : aa.z * v.z;
    v.w = v.w * dinv + bb.w; v.w = (v.w >= 0.f) ? v.w : aa.w * v.w;
    ((float4*)out)[(size_t)node * 16 + q] = v;
}

// ---------------- launch ----------------

extern "C" void kernel_launch(void* const* d_in, const int* in_sizes, int n_in,
                              void* d_out, int out_size) {
    const float* x  = (const float*)d_in[0];
    const int*   ei = (const int*)d_in[1];     // int32 (JAX x64 disabled)
    const float* W1 = (const float*)d_in[2];
    const float* b1 = (const float*)d_in[3];
    const float* a1 = (const float*)d_in[4];
    const float* W2 = (const float*)d_in[5];
    const float* b2 = (const float*)d_in[6];
    const float* a2 = (const float*)d_in[7];
    float* out = (float*)d_out;

    int n = in_sizes[0] / D;
    int E = in_sizes[1] / 2;

    int nb_n   = (n + 255) / 256;
    int nb_e   = (E + 255) / 256;
    int nb_gm  = (n + 63) / 64;
    int nb_sc  = (int)(((long long)E * 16 + 255) / 256);
    int nb_epi = (int)(((long long)n * 16 + 255) / 256);

    k_init_deg<<<nb_n, 256>>>(n);
    k_count   <<<nb_e, 256>>>(ei, E);
    k_dinv    <<<nb_n, 256>>>(n);

    // layer 1
    k_gemm   <<<nb_gm, 256>>>(x, W1, b1, a1, n, 0);
    k_scatter<<<nb_sc, 256>>>(ei, E);

    // layer 2 (layer-1 epilogue fused into GEMM staging)
    k_gemm   <<<nb_gm, 256>>>(x, W2, b1, a1, n, 1);
    k_scatter<<<nb_sc, 256>>>(ei, E);
    k_epi    <<<nb_epi, 256>>>(b2, a2, out, n);
}

// round 15
// speedup vs baseline: 2.0398x; 1.2821x over previous
#include <cuda_runtime.h>
#include <cstdint>

#define N_MAX 100000
#define D 64

__device__ __align__(16) int   g_deg [N_MAX];
__device__ __align__(16) float g_dinv[N_MAX];
__device__ __align__(16) float g_hs  [N_MAX * D];
__device__ __align__(16) float g_agg [N_MAX * D];

// ---------------- degree / norm ----------------

__global__ void k_init_deg(int n) {
    int i = blockIdx.x * blockDim.x + threadIdx.x;
    if (i < n) g_deg[i] = 1;                 // self-loop
}

__global__ void k_count(const int* __restrict__ ei, int E) {
    int e = blockIdx.x * blockDim.x + threadIdx.x;
    if (e < E) atomicAdd(&g_deg[ei[E + e]], 1);
}

__global__ void k_dinv(int n) {
    int i = blockIdx.x * blockDim.x + threadIdx.x;
    if (i < n) g_dinv[i] = rsqrtf((float)g_deg[i]);
}

// ---------------- fused GEMM, 4x4 register blocking (conflict-free) --------
// mode 0: in = X; mode 1: in = prelu(g_agg * dinv + b, a) (fused L1 epilogue)
// output: hs = (in @ W) * dinv ; agg = hs (self-loop init)
//
// Thread (tn = t>>4, tj = t&15): nodes [4tn,4tn+4), columns {tj+16*dc}.
// W rows tj+16dc with 68-word stride -> bank group 17(tj+16dc)+k4 = tj+4dc+k4
// mod 8: bijective per 8-lane phase -> conflict-free LDS.128.
// xs padded to 17 float4/row (68 words) so the 2 warp x-addresses differ in bank.

__global__ void __launch_bounds__(256, 2)
k_gemm(const float* __restrict__ X, const float* __restrict__ W,
       const float* __restrict__ bp, const float* __restrict__ ap,
       int n, int mode)
{
    __shared__ __align__(16) float  Wt[D][68];    // Wt[j][k] = W[k*64+j]
    __shared__ __align__(16) float4 xs[64][17];   // padded row: 68 words
    int t = threadIdx.x;

    // stage W transposed (coalesced reads)
    #pragma unroll
    for (int r = 0; r < 16; r++) {
        int i = t + 256 * r;
        Wt[i & 63][i >> 6] = W[i];
    }

    int base = blockIdx.x * 64;

    // stage input tile (coalesced float4), fusing layer-1 epilogue in mode 1
    #pragma unroll
    for (int r = 0; r < 4; r++) {
        int i = t + 256 * r;
        int node = base + (i >> 4);
        int k4 = i & 15;
        float4 v = make_float4(0.f, 0.f, 0.f, 0.f);
        if (node < n) {
            if (mode == 0) {
                v = ((const float4*)X)[(size_t)node * 16 + k4];
            } else {
                v = ((const float4*)g_agg)[(size_t)node * 16 + k4];
                float dv = g_dinv[node];
                float4 bb = ((const float4*)bp)[k4];
                float4 aa = ((const float4*)ap)[k4];
                v.x = v.x * dv + bb.x; v.x = (v.x >= 0.f) ? v.x : aa.x * v.x;
                v.y = v.y * dv + bb.y; v.y = (v.y >= 0.f) ? v.y : aa.y * v.y;
                v.z = v.z * dv + bb.z; v.z = (v.z >= 0.f) ? v.z : aa.z * v.z;
                v.w = v.w * dv + bb.w; v.w = (v.w >= 0.f) ? v.w : aa.w * v.w;
            }
        }
        xs[i >> 4][k4] = v;
    }
    __syncthreads();

    int tj = t & 15, tn = t >> 4;
    int n0 = 4 * tn;

    // acc{q}.{x,y,z,w} = node n0+q, columns tj+{0,16,32,48}
    float4 acc0 = make_float4(0.f,0.f,0.f,0.f);
    float4 acc1 = acc0, acc2 = acc0, acc3 = acc0;

    #pragma unroll
    for (int k4 = 0; k4 < 16; k4++) {
        float4 x0 = xs[n0 + 0][k4];
        float4 x1 = xs[n0 + 1][k4];
        float4 x2 = xs[n0 + 2][k4];
        float4 x3 = xs[n0 + 3][k4];
        float4 w0 = *(const float4*)&Wt[tj +  0][4 * k4];
        float4 w1 = *(const float4*)&Wt[tj + 16][4 * k4];
        float4 w2 = *(const float4*)&Wt[tj + 32][4 * k4];
        float4 w3 = *(const float4*)&Wt[tj + 48][4 * k4];

        acc0.x = fmaf(x0.x, w0.x, acc0.x); acc0.x = fmaf(x0.y, w0.y, acc0.x);
        acc0.x = fmaf(x0.z, w0.z, acc0.x); acc0.x = fmaf(x0.w, w0.w, acc0.x);
        acc0.y = fmaf(x0.x, w1.x, acc0.y); acc0.y = fmaf(x0.y, w1.y, acc0.y);
        acc0.y = fmaf(x0.z, w1.z, acc0.y); acc0.y = fmaf(x0.w, w1.w, acc0.y);
        acc0.z = fmaf(x0.x, w2.x, acc0.z); acc0.z = fmaf(x0.y, w2.y, acc0.z);
        acc0.z = fmaf(x0.z, w2.z, acc0.z); acc0.z = fmaf(x0.w, w2.w, acc0.z);
        acc0.w = fmaf(x0.x, w3.x, acc0.w); acc0.w = fmaf(x0.y, w3.y, acc0.w);
        acc0.w = fmaf(x0.z, w3.z, acc0.w); acc0.w = fmaf(x0.w, w3.w, acc0.w);

        acc1.x = fmaf(x1.x, w0.x, acc1.x); acc1.x = fmaf(x1.y, w0.y, acc1.x);
        acc1.x = fmaf(x1.z, w0.z, acc1.x); acc1.x = fmaf(x1.w, w0.w, acc1.x);
        acc1.y = fmaf(x1.x, w1.x, acc1.y); acc1.y = fmaf(x1.y, w1.y, acc1.y);
        acc1.y = fmaf(x1.z, w1.z, acc1.y); acc1.y = fmaf(x1.w, w1.w, acc1.y);
        acc1.z = fmaf(x1.x, w2.x, acc1.z); acc1.z = fmaf(x1.y, w2.y, acc1.z);
        acc1.z = fmaf(x1.z, w2.z, acc1.z); acc1.z = fmaf(x1.w, w2.w, acc1.z);
        acc1.w = fmaf(x1.x, w3.x, acc1.w); acc1.w = fmaf(x1.y, w3.y, acc1.w);
        acc1.w = fmaf(x1.z, w3.z, acc1.w); acc1.w = fmaf(x1.w, w3.w, acc1.w);

        acc2.x = fmaf(x2.x, w0.x, acc2.x); acc2.x = fmaf(x2.y, w0.y, acc2.x);
        acc2.x = fmaf(x2.z, w0.z, acc2.x); acc2.x = fmaf(x2.w, w0.w, acc2.x);
        acc2.y = fmaf(x2.x, w1.x, acc2.y); acc2.y = fmaf(x2.y, w1.y, acc2.y);
        acc2.y = fmaf(x2.z, w1.z, acc2.y); acc2.y = fmaf(x2.w, w1.w, acc2.y);
        acc2.z = fmaf(x2.x, w2.x, acc2.z); acc2.z = fmaf(x2.y, w2.y, acc2.z);
        acc2.z = fmaf(x2.z, w2.z, acc2.z); acc2.z = fmaf(x2.w, w2.w, acc2.z);
        acc2.w = fmaf(x2.x, w3.x, acc2.w); acc2.w = fmaf(x2.y, w3.y, acc2.w);
        acc2.w = fmaf(x2.z, w3.z, acc2.w); acc2.w = fmaf(x2.w, w3.w, acc2.w);

        acc3.x = fmaf(x3.x, w0.x, acc3.x); acc3.x = fmaf(x3.y, w0.y, acc3.x);
        acc3.x = fmaf(x3.z, w0.z, acc3.x); acc3.x = fmaf(x3.w, w0.w, acc3.x);
        acc3.y = fmaf(x3.x, w1.x, acc3.y); acc3.y = fmaf(x3.y, w1.y, acc3.y);
        acc3.y = fmaf(x3.z, w1.z, acc3.y); acc3.y = fmaf(x3.w, w1.w, acc3.y);
        acc3.z = fmaf(x3.x, w2.x, acc3.z); acc3.z = fmaf(x3.y, w2.y, acc3.z);
        acc3.z = fmaf(x3.z, w2.z, acc3.z); acc3.z = fmaf(x3.w, w2.w, acc3.z);
        acc3.w = fmaf(x3.x, w3.x, acc3.w); acc3.w = fmaf(x3.y, w3.y, acc3.w);
        acc3.w = fmaf(x3.z, w3.z, acc3.w); acc3.w = fmaf(x3.w, w3.w, acc3.w);
    }

    float4 accs[4] = {acc0, acc1, acc2, acc3};
    #pragma unroll
    for (int q = 0; q < 4; q++) {
        int node = base + n0 + q;
        if (node < n) {
            float dv = g_dinv[node];
            size_t o = (size_t)node * D + tj;
            float v0 = accs[q].x * dv;
            float v1 = accs[q].y * dv;
            float v2 = accs[q].z * dv;
            float v3 = accs[q].w * dv;
            g_hs[o +  0] = v0;  g_agg[o +  0] = v0;
            g_hs[o + 16] = v1;  g_agg[o + 16] = v1;
            g_hs[o + 32] = v2;  g_agg[o + 32] = v2;
            g_hs[o + 48] = v3;  g_agg[o + 48] = v3;
        }
    }
}

// ---------------- edge scatter: agg[dst] += hs[src] ----------------

__global__ void k_scatter(const int* __restrict__ ei, int E) {
    int tid = blockIdx.x * blockDim.x + threadIdx.x;
    int e = tid >> 4;
    if (e >= E) return;
    int lane = tid & 15;
    int src = ei[e];
    int dst = ei[E + e];
    float4 v = ((const float4*)(g_hs + (size_t)src * D))[lane];
    float* p = g_agg + (size_t)dst * D + lane * 4;
    unsigned long long gp;
    asm volatile("cvta.to.global.u64 %0, %1;" : "=l"(gp) : "l"(p));
    asm volatile("red.global.add.v4.f32 [%0], {%1,%2,%3,%4};"
                 :: "l"(gp), "f"(v.x), "f"(v.y), "f"(v.z), "f"(v.w)
                 : "memory");
}

// ---------------- final epilogue: out = prelu(agg*dinv + b, a) ----------------

__global__ void k_epi(const float* __restrict__ b, const float* __restrict__ a,
                      float* __restrict__ out, int n) {
    int tid = blockIdx.x * blockDim.x + threadIdx.x;
    int node = tid >> 4;
    if (node >= n) return;
    int q = tid & 15;
    float dinv = g_dinv[node];
    float4 v  = ((const float4*)g_agg)[(size_t)node * 16 + q];
    float4 bb = ((const float4*)b)[q];
    float4 aa = ((const float4*)a)[q];
    v.x = v.x * dinv + bb.x; v.x = (v.x >= 0.f) ? v.x : aa.x * v.x;
    v.y = v.y * dinv + bb.y; v.y = (v.y >= 0.f) ? v.y : aa.y * v.y;
    v.z = v.z * dinv + bb.z; v.z = (v.z >= 0.f) ? v.z : aa.z * v.z;
    v.w = v.w * dinv + bb.w; v.w = (v.w >= 0.f) ? v.w : aa.w * v.w;
    ((float4*)out)[(size_t)node * 16 + q] = v;
}

// ---------------- launch ----------------

extern "C" void kernel_launch(void* const* d_in, const int* in_sizes, int n_in,
                              void* d_out, int out_size) {
    const float* x  = (const float*)d_in[0];
    const int*   ei = (const int*)d_in[1];     // int32 (JAX x64 disabled)
    const float* W1 = (const float*)d_in[2];
    const float* b1 = (const float*)d_in[3];
    const float* a1 = (const float*)d_in[4];
    const float* W2 = (const float*)d_in[5];
    const float* b2 = (const float*)d_in[6];
    const float* a2 = (const float*)d_in[7];
    float* out = (float*)d_out;

    int n = in_sizes[0] / D;
    int E = in_sizes[1] / 2;

    int nb_n   = (n + 255) / 256;
    int nb_e   = (E + 255) / 256;
    int nb_gm  = (n + 63) / 64;
    int nb_sc  = (int)(((long long)E * 16 + 255) / 256);
    int nb_epi = (int)(((long long)n * 16 + 255) / 256);

    k_init_deg<<<nb_n, 256>>>(n);
    k_count   <<<nb_e, 256>>>(ei, E);
    k_dinv    <<<nb_n, 256>>>(n);

    // layer 1
    k_gemm   <<<nb_gm, 256>>>(x, W1, b1, a1, n, 0);
    k_scatter<<<nb_sc, 256>>>(ei, E);

    // layer 2 (layer-1 epilogue fused into GEMM staging)
    k_gemm   <<<nb_gm, 256>>>(x, W2, b1, a1, n, 1);
    k_scatter<<<nb_sc, 256>>>(ei, E);
    k_epi    <<<nb_epi, 256>>>(b2, a2, out, n);
}